// round 8
// baseline (speedup 1.0000x reference)
#include <cuda_runtime.h>
#include <cuda_pipeline.h>
#include <math.h>

// Shapes
#define Bn 128
#define Tn 64
#define Un 256
#define Vn 48
#define Sn 192
#define CL 8
#define NG 16
#define NGRID 152
#define NTHR 512

typedef unsigned long long ull;
typedef unsigned int u32;

// ---------------- device globals ----------------
__device__ float    g_proj[(size_t)NG * CL * 8 * Tn * 128];  // [g][q][r][t][c]
__device__ float    g_embP[CL * Vn * 128];                   // [q][v][c]
__device__ float    g_wC[CL * Un * 128];                     // [q][k][c]
__device__ int      g_ts[Bn];

// ---------------- helpers ----------------
__device__ __forceinline__ ull pack2(float x, float y) {
    ull r; asm("mov.b64 %0, {%1, %2};" : "=l"(r) : "f"(x), "f"(y)); return r;
}
__device__ __forceinline__ void ffma2(ull& d, ull a, ull b) {
    asm("fma.rn.f32x2 %0, %1, %2, %0;" : "+l"(d) : "l"(a), "l"(b));
}
__device__ __forceinline__ ull add2(ull a, ull b) {
    ull r; asm("add.rn.f32x2 %0, %1, %2;" : "=l"(r) : "l"(a), "l"(b)); return r;
}
__device__ __forceinline__ float2 unpack2(ull v) {
    float2 f; asm("mov.b64 {%0, %1}, %2;" : "=f"(f.x), "=f"(f.y) : "l"(v)); return f;
}
__device__ __forceinline__ u32 smem_u32(const void* p) {
    u32 a; asm("{ .reg .u64 t; cvta.to.shared.u64 t, %1; cvt.u32.u64 %0, t; }" : "=r"(a) : "l"(p)); return a;
}
__device__ __forceinline__ void stc_u64(u32 la, int rank, ull v) {
    u32 ra; asm("mapa.shared::cluster.u32 %0, %1, %2;" : "=r"(ra) : "r"(la), "r"(rank));
    asm volatile("st.shared::cluster.u64 [%0], %1;" :: "r"(ra), "l"(v));
}
__device__ __forceinline__ void stc_f32(u32 la, int rank, float v) {
    u32 ra; asm("mapa.shared::cluster.u32 %0, %1, %2;" : "=r"(ra) : "r"(la), "r"(rank));
    asm volatile("st.shared::cluster.f32 [%0], %1;" :: "r"(ra), "f"(v));
}
__device__ __forceinline__ void stc_u32(u32 la, int rank, u32 v) {
    u32 ra; asm("mapa.shared::cluster.u32 %0, %1, %2;" : "=r"(ra) : "r"(la), "r"(rank));
    asm volatile("st.shared::cluster.u32 [%0], %1;" :: "r"(ra), "r"(v));
}
__device__ __forceinline__ u32 ld_vol_sh(u32 addr) {
    u32 v; asm volatile("ld.volatile.shared.u32 %0, [%1];" : "=r"(v) : "r"(addr)); return v;
}
__device__ __forceinline__ float sigm(float x) { return 1.0f / (1.0f + expf(-x)); }

// ---------------- nop (ncu launch alignment) ----------------
__global__ void k_nop() {}

// ---------------- fused prep ----------------
__global__ void k_prep(const int* __restrict__ word_ids,
                       const float* __restrict__ embed,
                       const float* __restrict__ W,
                       const float* __restrict__ bias,
                       const float* __restrict__ Uw) {
    int bi = blockIdx.x, tid = threadIdx.x;
    if (bi == 0) {
        if (tid < Bn) {
            int c = 0;
            for (int t = 0; t < Tn; t++) c += (word_ids[tid * Tn + t] != 0);
            g_ts[tid] = c;
        }
        return;
    }
    if (bi <= 192) {
        int e = bi - 1;
        int t = e >> 2;
        int col = (e & 3) * 256 + tid;
        float acc = bias[col];
        for (int k = 0; k < 256; k++)
            acc += embed[t * 256 + k] * W[k * 1024 + col];
        int unit = col & 255, gate = col >> 8;
        int q = unit >> 5, ul = unit & 31;
        g_embP[(q * Vn + t) * 128 + ul * 4 + gate] = acc;
        return;
    }
    int idx = (bi - 193) * 256 + tid;
    int q = idx >> 15, r = idx & 32767;
    int k = r >> 7, c = r & 127;
    int gate = c & 3, ul = c >> 2;
    int col = gate * 256 + 32 * q + ul;
    g_wC[idx] = Uw[k * 1024 + col];
}

// ---------------- proj GEMM: 128x128 tile, f32x2, cp.async double buffer ----------------
__global__ void __launch_bounds__(256) k_proj(const float* __restrict__ A,
                                              const float* __restrict__ W) {
    __shared__ __align__(16) float As[2][128 * 16];
    __shared__ __align__(16) float Bs[2][16 * 128];
    int row0 = blockIdx.y * 128, col0 = blockIdx.x * 128;
    int tid = threadIdx.x;
    int tr = tid >> 4, tc = tid & 15;
    int lr = tid >> 1, lk = (tid & 1) * 8;
    int lkb = tid >> 4, lcb = (tid & 15) * 8;

    ull acc[8][4];
#pragma unroll
    for (int i = 0; i < 8; i++)
#pragma unroll
        for (int j = 0; j < 4; j++) acc[i][j] = 0ull;

    auto stage = [&](int ks) {
        int buf = ks & 1;
        int k0 = ks * 16;
        __pipeline_memcpy_async(&As[buf][lr * 16 + lk],
                                &A[(size_t)(row0 + lr) * 768 + k0 + lk], 16);
        __pipeline_memcpy_async(&As[buf][lr * 16 + lk + 4],
                                &A[(size_t)(row0 + lr) * 768 + k0 + lk + 4], 16);
        __pipeline_memcpy_async(&Bs[buf][lkb * 128 + lcb],
                                &W[(size_t)(256 + k0 + lkb) * 1024 + col0 + lcb], 16);
        __pipeline_memcpy_async(&Bs[buf][lkb * 128 + lcb + 4],
                                &W[(size_t)(256 + k0 + lkb) * 1024 + col0 + lcb + 4], 16);
        __pipeline_commit();
    };

    stage(0);
    for (int ks = 0; ks < 48; ks++) {
        if (ks < 47) { stage(ks + 1); __pipeline_wait_prior(1); }
        else         { __pipeline_wait_prior(0); }
        __syncthreads();
        int buf = ks & 1;
        const float* Ab = &As[buf][tr * 8 * 16];
        const ull*   Bb = (const ull*)&Bs[buf][tc * 8];
#pragma unroll
        for (int kk = 0; kk < 16; kk++) {
            ulonglong2 b01 = *(const ulonglong2*)(Bb + (size_t)kk * 64);
            ulonglong2 b23 = *(const ulonglong2*)(Bb + (size_t)kk * 64 + 2);
            ull bv[4] = {b01.x, b01.y, b23.x, b23.y};
#pragma unroll
            for (int i = 0; i < 8; i++) {
                float a = Ab[i * 16 + kk];
                ull ap = pack2(a, a);
                ffma2(acc[i][0], ap, bv[0]);
                ffma2(acc[i][1], ap, bv[1]);
                ffma2(acc[i][2], ap, bv[2]);
                ffma2(acc[i][3], ap, bv[3]);
            }
        }
        __syncthreads();
    }

#pragma unroll
    for (int i = 0; i < 8; i++) {
        int row = row0 + tr * 8 + i;
        int b = row >> 6, t = row & 63;
        int g = b >> 3, rr = b & 7;
#pragma unroll
        for (int j = 0; j < 4; j++) {
            float2 v = unpack2(acc[i][j]);
            int col = col0 + tc * 8 + 2 * j;
#pragma unroll
            for (int e = 0; e < 2; e++) {
                int cc = col + e;
                int unit = cc & 255, gate = cc >> 8;
                int q = unit >> 5, ul = unit & 31;
                g_proj[((((size_t)(g * CL + q) * 8 + rr) * Tn + t) * 128) + ul * 4 + gate] =
                    (e == 0) ? v.x : v.y;
            }
        }
    }
}

// ---------------- persistent cluster decode loop: 512 threads, split-k 8 ----------------
// smem floats:
#define W2S_OFF  0        // 32768  packed Uw slice (ull view)
#define HD_OFF   32768    // 8192   h exchange (dup), 2 par x 2048 ull ([k][r])
#define ZP_OFF   40960    // 8192   z partials, 8 slices x 512 ull ([sl][r][p])
#define WOS_OFF  49152    // 1536   Wo slice [ul][v]
#define EPP_OFF  50688    // 1024
#define PPP_OFF  51712    // 1024
#define PLOG_OFF 52736    // 768    2 par x [q][48]
#define H2S_OFF  53504    // 256    [pu][pr]
#define CST_OFF  53760    // 256
#define BOS_OFF  54016    // 48
#define CTRL_OFF 54064    // 16
#define SMEMF    54080
#define SMEMB    (SMEMF * 4)

__global__ void __launch_bounds__(NTHR, 1) __cluster_dims__(CL, 1, 1)
k_loop(const float* __restrict__ Wo, const float* __restrict__ bo,
       float* __restrict__ out) {
    extern __shared__ __align__(16) float smf[];
    int tid = threadIdx.x;
    u32 q; asm("mov.u32 %0, %%cluster_ctarank;" : "=r"(q));
    int g = blockIdx.x >> 3;
    if (g >= NG) return;
    u32 smbase = smem_u32(smf);

    float* epp  = smf + EPP_OFF;
    float* ppp  = smf + PPP_OFF;
    float* WoS  = smf + WOS_OFF;
    float* h2s  = smf + H2S_OFF;
    float* cst  = smf + CST_OFF;
    float* bos  = smf + BOS_OFF;
    volatile u32* ctrlL = (volatile u32*)(smf + CTRL_OFF);
    const ull* w2u = (const ull*)(smf + W2S_OFF);
    ull* hdA = (ull*)(smf + HD_OFF);
    ull* zpu = (ull*)(smf + ZP_OFF);

    // ---- init ----
    {
        const float* wsrc = g_wC + (size_t)q * 32768;
        for (int i = tid * 4; i < 32768; i += NTHR * 4)
            __pipeline_memcpy_async(&smf[W2S_OFF + i], &wsrc[i], 16);
        __pipeline_commit();
        for (int i = tid; i < 1536; i += NTHR) WoS[i] = Wo[q * 1536 + i];
        if (tid < Vn) bos[tid] = bo[tid];
        for (int i = tid; i < 2048; i += NTHR) hdA[i] = 0ull;   // parity 0 = h(0) = 0
        if (tid < 256) cst[tid] = 0.f;
        if (tid < 8) ctrlL[tid] = 1u;   // tag 0, adj 0, tgt BOS
        __pipeline_wait_prior(0);
        __syncthreads();
        asm volatile("barrier.cluster.arrive.aligned;" ::: "memory");
        asm volatile("barrier.cluster.wait.aligned;" ::: "memory");
    }

    int p = tid & 63, kq = tid >> 6;      // kq 0..7 : 8-way split-k (32 k each)
    int wrp = tid >> 5;                   // warp id 0..15
    int rrow = wrp & 7;                   // prefetch row
    int c4 = (tid & 31) * 4;
    int pu = tid >> 3, pr = tid & 7;      // pointwise (tid<256)
    int row = g * 8 + (int)q;
    int hai = 0, ts = 0;
    if (tid < 32) ts = g_ts[row];
    u32 ctrl_addr = smbase + CTRL_OFF * 4 + rrow * 4;
    const ull* wt = w2u + kq * 2048 + p;

    for (int s = 0; s < Sn; s++) {
        const ulonglong2* hp =
            (const ulonglong2*)(hdA + (s & 1) * 2048 + kq * 256);

        // ---- z: 128 gate-cols x 8 rows, split-k(8): 32 k per thread ----
        ull a0 = 0, a1 = 0, a2 = 0, a3 = 0, a4 = 0, a5 = 0, a6 = 0, a7 = 0;
#pragma unroll 8
        for (int kk = 0; kk < 16; kk++) {
            ull w = wt[kk * 64];
            ulonglong2 h01 = hp[kk * 4 + 0], h23 = hp[kk * 4 + 1];
            ulonglong2 h45 = hp[kk * 4 + 2], h67 = hp[kk * 4 + 3];
            ffma2(a0, h01.x, w); ffma2(a1, h01.y, w);
            ffma2(a2, h23.x, w); ffma2(a3, h23.y, w);
            ffma2(a4, h45.x, w); ffma2(a5, h45.y, w);
            ffma2(a6, h67.x, w); ffma2(a7, h67.y, w);
        }
        // mid-loop: spin on LOCAL ctrl word + prefetch ep (warps 0-7) / pp (warps 8-15)
        {
            u32 w;
            do { w = ld_vol_sh(ctrl_addr); } while ((int)(w >> 12) < s);
            int tgt = (int)(w & 63u), adjv = (int)((w >> 6) & 63u);
            if (wrp < 8) {
                __pipeline_memcpy_async(&epp[rrow * 128 + c4],
                                        &g_embP[((int)q * Vn + tgt) * 128 + c4], 16);
            } else {
                __pipeline_memcpy_async(&ppp[rrow * 128 + c4],
                    &g_proj[((((size_t)(g * CL + (int)q) * 8 + rrow) * Tn + adjv) * 128) + c4], 16);
            }
            __pipeline_commit();
        }
#pragma unroll 8
        for (int kk = 16; kk < 32; kk++) {
            ull w = wt[kk * 64];
            ulonglong2 h01 = hp[kk * 4 + 0], h23 = hp[kk * 4 + 1];
            ulonglong2 h45 = hp[kk * 4 + 2], h67 = hp[kk * 4 + 3];
            ffma2(a0, h01.x, w); ffma2(a1, h01.y, w);
            ffma2(a2, h23.x, w); ffma2(a3, h23.y, w);
            ffma2(a4, h45.x, w); ffma2(a5, h45.y, w);
            ffma2(a6, h67.x, w); ffma2(a7, h67.y, w);
        }
        __pipeline_wait_prior(0);
        {
            ull* zd = zpu + kq * 512 + p;   // [sl][r][p]
            zd[0 * 64] = a0; zd[1 * 64] = a1; zd[2 * 64] = a2; zd[3 * 64] = a3;
            zd[4 * 64] = a4; zd[5 * 64] = a5; zd[6 * 64] = a6; zd[7 * 64] = a7;
        }
        __syncthreads();

        // ---- pointwise (tid<256: unit-in-slice pu, row pr) ----
        if (tid < 256) {
            ulonglong2 k0 = *(const ulonglong2*)(zpu + 0 * 512 + pr * 64 + 2 * pu);
            ulonglong2 k1 = *(const ulonglong2*)(zpu + 1 * 512 + pr * 64 + 2 * pu);
            ulonglong2 k2 = *(const ulonglong2*)(zpu + 2 * 512 + pr * 64 + 2 * pu);
            ulonglong2 k3 = *(const ulonglong2*)(zpu + 3 * 512 + pr * 64 + 2 * pu);
            ulonglong2 k4 = *(const ulonglong2*)(zpu + 4 * 512 + pr * 64 + 2 * pu);
            ulonglong2 k5 = *(const ulonglong2*)(zpu + 5 * 512 + pr * 64 + 2 * pu);
            ulonglong2 k6 = *(const ulonglong2*)(zpu + 6 * 512 + pr * 64 + 2 * pu);
            ulonglong2 k7 = *(const ulonglong2*)(zpu + 7 * 512 + pr * 64 + 2 * pu);
            ull s0 = add2(add2(add2(k0.x, k1.x), add2(k2.x, k3.x)),
                          add2(add2(k4.x, k5.x), add2(k6.x, k7.x)));
            ull s1 = add2(add2(add2(k0.y, k1.y), add2(k2.y, k3.y)),
                          add2(add2(k4.y, k5.y), add2(k6.y, k7.y)));
            float4 ep = *(const float4*)&epp[pr * 128 + 4 * pu];
            float4 pq = *(const float4*)&ppp[pr * 128 + 4 * pu];
            float2 zif = unpack2(s0);
            float2 zgo = unpack2(s1);
            float zi = zif.x + ep.x + pq.x;
            float zf = zif.y + ep.y + pq.y;
            float zg = zgo.x + ep.z + pq.z;
            float zo = zgo.y + ep.w + pq.w;
            float cold = cst[tid];
            float c2 = sigm(zf) * cold + sigm(zi) * tanhf(zg);
            float h2v = sigm(zo) * tanhf(c2);
            cst[tid] = c2;
            h2s[pu * 8 + pr] = h2v;
            ull hh = pack2(h2v, h2v);
            u32 la = smbase + HD_OFF * 4 +
                     ((((s + 1) & 1) * 2048 + (32 * (int)q + pu) * 8 + pr) * 8);
#pragma unroll
            for (int d = 0; d < CL; d++) stc_u64(la, d, hh);
        }
        __syncthreads();

        // ---- partial logits: 512 threads = one (row, v) pair each ----
        {
            int v = tid & 63, rr2 = tid >> 6;   // rr2 0..7
            if (v < Vn) {
                float pa0 = 0.f;
#pragma unroll 8
                for (int ul = 0; ul < 32; ul++)
                    pa0 += h2s[ul * 8 + rr2] * WoS[ul * Vn + v];
                u32 pa = smbase + (PLOG_OFF + (s & 1) * 384 + (int)q * Vn + v) * 4;
                stc_f32(pa, rr2, pa0);
            }
        }
        asm volatile("barrier.cluster.arrive.aligned;" ::: "memory");
        asm volatile("barrier.cluster.wait.aligned;" ::: "memory");

        // ---- owner reduce + argmax + DSMEM ctrl publish ----
        {
            const float* plogB = smf + PLOG_OFF + (s & 1) * 384;
            float* fsm = epp;   // reuse (consumed this step)
            if (tid < Vn) {
                float sum = bos[tid];
#pragma unroll
                for (int qq = 0; qq < CL; qq++) sum += plogB[qq * Vn + tid];
                fsm[tid] = sum;
            }
            __syncthreads();
            if (tid < 32) {
                float bv = fsm[tid]; int bi = tid;
                if (tid < 16) {
                    float x2 = fsm[tid + 32];
                    if (x2 > bv) { bv = x2; bi = tid + 32; }
                }
#pragma unroll
                for (int off = 16; off; off >>= 1) {
                    float ov = __shfl_xor_sync(0xffffffffu, bv, off);
                    int   oi = __shfl_xor_sync(0xffffffffu, bi, off);
                    if (ov > bv || (ov == bv && oi < bi)) { bv = ov; bi = oi; }
                }
                int preds = bi;
                int res = (hai == ts) ? 0 : preds;
                if (tid == 0) out[row * Sn + s] = (float)res;
                int inc = (preds == 2 && hai < ts) ? 1 : 0;
                hai += inc;
                int adjn = (hai < ts) ? hai : hai - 1;
                u32 word = ((u32)(s + 1) << 12) | ((u32)adjn << 6) | (u32)preds;
                if (tid < 8) stc_u32(smbase + CTRL_OFF * 4 + (int)q * 4, tid, word);
            }
            __syncthreads();
        }
    }
}

// ---------------- launch ----------------
extern "C" void kernel_launch(void* const* d_in, const int* in_sizes, int n_in,
                              void* d_out, int out_size) {
    (void)in_sizes; (void)n_in; (void)out_size;
    const float* inputs   = (const float*)d_in[0];
    const int*   word_ids = (const int*)d_in[1];
    const float* embed    = (const float*)d_in[2];
    const float* W        = (const float*)d_in[3];
    const float* Uw       = (const float*)d_in[4];
    const float* bias     = (const float*)d_in[5];
    const float* Wo       = (const float*)d_in[6];
    const float* bo       = (const float*)d_in[7];
    float* out = (float*)d_out;

    static int attr_done = 0;
    if (!attr_done) {
        cudaFuncSetAttribute(k_loop, cudaFuncAttributeMaxDynamicSharedMemorySize, SMEMB);
        attr_done = 1;
    }
    k_nop<<<1, 32>>>();
    k_prep<<<1217, 256>>>(word_ids, embed, W, bias, Uw);
    k_proj<<<dim3(8, 64), 256>>>(inputs, W);
    k_loop<<<NGRID, NTHR, SMEMB>>>(Wo, bo, out);
}

// round 9
// speedup vs baseline: 1.2570x; 1.2570x over previous
#include <cuda_runtime.h>
#include <cuda_pipeline.h>
#include <math.h>

// Shapes
#define Bn 128
#define Tn 64
#define Un 256
#define Vn 48
#define Sn 192
#define CL 8
#define NG 16
#define NGRID 152
#define NTHR 288   // 8 worker warps + 1 control warp

typedef unsigned long long ull;
typedef unsigned int u32;

// ---------------- device globals ----------------
__device__ float    g_proj[(size_t)NG * CL * 8 * Tn * 128];  // [g][q][r][t][c]
__device__ float    g_embP[CL * Vn * 128];                   // [q][v][c]
__device__ float    g_wC[CL * Un * 128];                     // [q][k][c]
__device__ int      g_ts[Bn];

// ---------------- helpers ----------------
__device__ __forceinline__ ull pack2(float x, float y) {
    ull r; asm("mov.b64 %0, {%1, %2};" : "=l"(r) : "f"(x), "f"(y)); return r;
}
__device__ __forceinline__ void ffma2(ull& d, ull a, ull b) {
    asm("fma.rn.f32x2 %0, %1, %2, %0;" : "+l"(d) : "l"(a), "l"(b));
}
__device__ __forceinline__ ull add2(ull a, ull b) {
    ull r; asm("add.rn.f32x2 %0, %1, %2;" : "=l"(r) : "l"(a), "l"(b)); return r;
}
__device__ __forceinline__ float2 unpack2(ull v) {
    float2 f; asm("mov.b64 {%0, %1}, %2;" : "=f"(f.x), "=f"(f.y) : "l"(v)); return f;
}
__device__ __forceinline__ u32 smem_u32(const void* p) {
    u32 a; asm("{ .reg .u64 t; cvta.to.shared.u64 t, %1; cvt.u32.u64 %0, t; }" : "=r"(a) : "l"(p)); return a;
}
__device__ __forceinline__ u32 mapa_(u32 la, u32 rank) {
    u32 ra; asm("mapa.shared::cluster.u32 %0, %1, %2;" : "=r"(ra) : "r"(la), "r"(rank)); return ra;
}
__device__ __forceinline__ void stc_u32(u32 la, int rank, u32 v) {
    u32 ra = mapa_(la, (u32)rank);
    asm volatile("st.shared::cluster.u32 [%0], %1;" :: "r"(ra), "r"(v));
}
__device__ __forceinline__ u32 ld_vol_sh(u32 addr) {
    u32 v; asm volatile("ld.volatile.shared.u32 %0, [%1];" : "=r"(v) : "r"(addr)); return v;
}
__device__ __forceinline__ void mbar_init_(u32 a, u32 cnt) {
    asm volatile("mbarrier.init.shared.b64 [%0], %1;" :: "r"(a), "r"(cnt) : "memory");
}
__device__ __forceinline__ void mbar_expect_(u32 a, u32 bytes) {
    asm volatile("mbarrier.arrive.expect_tx.shared.b64 _, [%0], %1;" :: "r"(a), "r"(bytes) : "memory");
}
__device__ __forceinline__ void mbar_wait_(u32 a, u32 ph) {
    u32 done;
    asm volatile("{\n\t.reg .pred p;\n\t"
                 "mbarrier.try_wait.parity.acquire.cta.shared::cta.b64 p, [%1], %2;\n\t"
                 "selp.b32 %0, 1, 0, p;\n\t}" : "=r"(done) : "r"(a), "r"(ph) : "memory");
    if (!done) {
        asm volatile("{\n\t.reg .pred P1;\n\t"
                     "WL_%=:\n\t"
                     "mbarrier.try_wait.parity.acquire.cta.shared::cta.b64 P1, [%0], %1, 0x989680;\n\t"
                     "@P1 bra.uni WD_%=;\n\t"
                     "bra.uni WL_%=;\n\t"
                     "WD_%=:\n\t}" :: "r"(a), "r"(ph) : "memory");
    }
}
__device__ __forceinline__ void bulk_dsmem_(u32 dst, u32 src, u32 bytes, u32 mbar) {
    asm volatile("cp.async.bulk.shared::cluster.shared::cta.mbarrier::complete_tx::bytes "
                 "[%0], [%1], %2, [%3];"
                 :: "r"(dst), "r"(src), "r"(bytes), "r"(mbar) : "memory");
}
#define BULK_COMMIT()     asm volatile("cp.async.bulk.commit_group;" ::: "memory")
#define BULK_WAIT_READ0() asm volatile("cp.async.bulk.wait_group.read 0;" ::: "memory")
#define FENCE_ASYNC()     asm volatile("fence.proxy.async.shared::cta;" ::: "memory")
__device__ __forceinline__ float sigm(float x) { return 1.0f / (1.0f + expf(-x)); }

// ---------------- nop (ncu launch alignment) ----------------
__global__ void k_nop() {}

// ---------------- fused prep ----------------
__global__ void k_prep(const int* __restrict__ word_ids,
                       const float* __restrict__ embed,
                       const float* __restrict__ W,
                       const float* __restrict__ bias,
                       const float* __restrict__ Uw) {
    int bi = blockIdx.x, tid = threadIdx.x;
    if (bi == 0) {
        if (tid < Bn) {
            int c = 0;
            for (int t = 0; t < Tn; t++) c += (word_ids[tid * Tn + t] != 0);
            g_ts[tid] = c;
        }
        return;
    }
    if (bi <= 192) {
        int e = bi - 1;
        int t = e >> 2;
        int col = (e & 3) * 256 + tid;
        float acc = bias[col];
        for (int k = 0; k < 256; k++)
            acc += embed[t * 256 + k] * W[k * 1024 + col];
        int unit = col & 255, gate = col >> 8;
        int q = unit >> 5, ul = unit & 31;
        g_embP[(q * Vn + t) * 128 + ul * 4 + gate] = acc;
        return;
    }
    int idx = (bi - 193) * 256 + tid;
    int q = idx >> 15, r = idx & 32767;
    int k = r >> 7, c = r & 127;
    int gate = c & 3, ul = c >> 2;
    int col = gate * 256 + 32 * q + ul;
    g_wC[idx] = Uw[k * 1024 + col];
}

// ---------------- proj GEMM: 128x128 tile, f32x2, cp.async double buffer ----------------
__global__ void __launch_bounds__(256) k_proj(const float* __restrict__ A,
                                              const float* __restrict__ W) {
    __shared__ __align__(16) float As[2][128 * 16];
    __shared__ __align__(16) float Bs[2][16 * 128];
    int row0 = blockIdx.y * 128, col0 = blockIdx.x * 128;
    int tid = threadIdx.x;
    int tr = tid >> 4, tc = tid & 15;
    int lr = tid >> 1, lk = (tid & 1) * 8;
    int lkb = tid >> 4, lcb = (tid & 15) * 8;

    ull acc[8][4];
#pragma unroll
    for (int i = 0; i < 8; i++)
#pragma unroll
        for (int j = 0; j < 4; j++) acc[i][j] = 0ull;

    auto stage = [&](int ks) {
        int buf = ks & 1;
        int k0 = ks * 16;
        __pipeline_memcpy_async(&As[buf][lr * 16 + lk],
                                &A[(size_t)(row0 + lr) * 768 + k0 + lk], 16);
        __pipeline_memcpy_async(&As[buf][lr * 16 + lk + 4],
                                &A[(size_t)(row0 + lr) * 768 + k0 + lk + 4], 16);
        __pipeline_memcpy_async(&Bs[buf][lkb * 128 + lcb],
                                &W[(size_t)(256 + k0 + lkb) * 1024 + col0 + lcb], 16);
        __pipeline_memcpy_async(&Bs[buf][lkb * 128 + lcb + 4],
                                &W[(size_t)(256 + k0 + lkb) * 1024 + col0 + lcb + 4], 16);
        __pipeline_commit();
    };

    stage(0);
    for (int ks = 0; ks < 48; ks++) {
        if (ks < 47) { stage(ks + 1); __pipeline_wait_prior(1); }
        else         { __pipeline_wait_prior(0); }
        __syncthreads();
        int buf = ks & 1;
        const float* Ab = &As[buf][tr * 8 * 16];
        const ull*   Bb = (const ull*)&Bs[buf][tc * 8];
#pragma unroll
        for (int kk = 0; kk < 16; kk++) {
            ulonglong2 b01 = *(const ulonglong2*)(Bb + (size_t)kk * 64);
            ulonglong2 b23 = *(const ulonglong2*)(Bb + (size_t)kk * 64 + 2);
            ull bv[4] = {b01.x, b01.y, b23.x, b23.y};
#pragma unroll
            for (int i = 0; i < 8; i++) {
                float a = Ab[i * 16 + kk];
                ull ap = pack2(a, a);
                ffma2(acc[i][0], ap, bv[0]);
                ffma2(acc[i][1], ap, bv[1]);
                ffma2(acc[i][2], ap, bv[2]);
                ffma2(acc[i][3], ap, bv[3]);
            }
        }
        __syncthreads();
    }

#pragma unroll
    for (int i = 0; i < 8; i++) {
        int row = row0 + tr * 8 + i;
        int b = row >> 6, t = row & 63;
        int g = b >> 3, rr = b & 7;
#pragma unroll
        for (int j = 0; j < 4; j++) {
            float2 v = unpack2(acc[i][j]);
            int col = col0 + tc * 8 + 2 * j;
#pragma unroll
            for (int e = 0; e < 2; e++) {
                int cc = col + e;
                int unit = cc & 255, gate = cc >> 8;
                int q = unit >> 5, ul = unit & 31;
                g_proj[((((size_t)(g * CL + q) * 8 + rr) * Tn + t) * 128) + ul * 4 + gate] =
                    (e == 0) ? v.x : v.y;
            }
        }
    }
}

// ---------------- persistent cluster decode loop ----------------
// smem floats:
#define W2S_OFF  0        // 32768  packed Uw slice (ull view)
#define HD_OFF   32768    // 8192   h exchange (dup), 2 par x [src q][32u][8r] ull
#define ZP_OFF   40960    // 4096   z partials (ull view) [kq][r][p]
#define WOS_OFF  45056    // 1536   Wo slice [ul][v]
#define EPP_OFF  46592    // 1024
#define PPP_OFF  47616    // 1024
#define PLG_OFF  48640    // 384    local plog partials [r][48]
#define PIN_OFF  49024    // 768    plog inbox, 2 par x [src][48]
#define H2S_OFF  49792    // 256    [pu][pr]
#define CST_OFF  50048    // 256
#define BOS_OFF  50304    // 48
#define CTRL_OFF 50352    // 16
#define MBAR_OFF 50368    // 16     4 mbarriers: h0,h1,p0,p1
#define SMEMF    50384
#define SMEMB    (SMEMF * 4)

#define HB_BYTES 2048
#define PL_BYTES 192
#define EXP_H    (7 * HB_BYTES)
#define EXP_P    (7 * PL_BYTES)

__global__ void __launch_bounds__(NTHR, 1) __cluster_dims__(CL, 1, 1)
k_loop(const float* __restrict__ Wo, const float* __restrict__ bo,
       float* __restrict__ out) {
    extern __shared__ __align__(16) float smf[];
    int tid = threadIdx.x;
    u32 q; asm("mov.u32 %0, %%cluster_ctarank;" : "=r"(q));
    int g = blockIdx.x >> 3;
    if (g >= NG) return;
    u32 smbase = smem_u32(smf);

    float* epp  = smf + EPP_OFF;
    float* ppp  = smf + PPP_OFF;
    float* WoS  = smf + WOS_OFF;
    float* h2s  = smf + H2S_OFF;
    float* cst  = smf + CST_OFF;
    float* bos  = smf + BOS_OFF;
    float* plg  = smf + PLG_OFF;
    volatile u32* ctrlL = (volatile u32*)(smf + CTRL_OFF);
    const ull* w2u = (const ull*)(smf + W2S_OFF);
    ull* hdA = (ull*)(smf + HD_OFF);
    ull* zpu = (ull*)(smf + ZP_OFF);

    u32 mbH[2] = { smbase + MBAR_OFF * 4 + 0, smbase + MBAR_OFF * 4 + 8 };
    u32 mbP[2] = { smbase + MBAR_OFF * 4 + 16, smbase + MBAR_OFF * 4 + 24 };

    // ---- init ----
    {
        const float* wsrc = g_wC + (size_t)q * 32768;
        for (int i = tid * 4; i < 32768; i += NTHR * 4)
            __pipeline_memcpy_async(&smf[W2S_OFF + i], &wsrc[i], 16);
        __pipeline_commit();
        for (int i = tid; i < 1536; i += NTHR) WoS[i] = Wo[q * 1536 + i];
        if (tid < Vn) bos[tid] = bo[tid];
        for (int i = tid; i < 2048; i += NTHR) hdA[i] = 0ull;   // parity 0 = h(0) = 0
        if (tid < 256) cst[tid] = 0.f;
        if (tid < 8) ctrlL[tid] = 1u;   // tag 0, adj 0, tgt BOS
        if (tid == 0) {
            mbar_init_(mbH[0], 1); mbar_init_(mbH[1], 1);
            mbar_init_(mbP[0], 1); mbar_init_(mbP[1], 1);
        }
        __pipeline_wait_prior(0);
        __syncthreads();
        asm volatile("barrier.cluster.arrive.aligned;" ::: "memory");
        asm volatile("barrier.cluster.wait.aligned;" ::: "memory");
    }

    int p = tid & 63, kq = tid >> 6;      // worker split-k(4)
    int rrow = (tid >> 5) & 7;            // worker warp -> polled/prefetch row
    int c4 = (tid & 31) * 4;
    int pu = tid >> 3, pr = tid & 7;      // pointwise (tid<256)
    int row = g * 8 + (int)q;
    int lane = tid - 256;                 // control warp lane (tid>=256)
    int hai = 0, ts = 0;
    if (tid >= 256) ts = g_ts[row];
    u32 ctrl_addr = smbase + CTRL_OFF * 4 + rrow * 4;

    for (int s = 0; s < Sn; s++) {
        if (tid < 256) {
            // ---- expect_tx posts (single thread) ----
            if (tid == 0) {
                mbar_expect_(mbP[s & 1], EXP_P);
                if (s + 1 < Sn) mbar_expect_(mbH[(s + 1) & 1], EXP_H);
            }
            // ---- wait h(s) gathered ----
            if (s > 0) mbar_wait_(mbH[s & 1], (u32)(((s - 1) >> 1) & 1));

            // ---- z: 128 gate-cols x 8 rows, split-k(4) ----
            const ull* wt = w2u + kq * 4096 + p;
            const ulonglong2* hp = (const ulonglong2*)(hdA + (s & 1) * 2048 + kq * 512);
            ull a0 = 0, a1 = 0, a2 = 0, a3 = 0, a4 = 0, a5 = 0, a6 = 0, a7 = 0;
#pragma unroll 8
            for (int kk = 0; kk < 32; kk++) {
                ull w = wt[kk * 64];
                ulonglong2 h01 = hp[kk * 4 + 0], h23 = hp[kk * 4 + 1];
                ulonglong2 h45 = hp[kk * 4 + 2], h67 = hp[kk * 4 + 3];
                ffma2(a0, h01.x, w); ffma2(a1, h01.y, w);
                ffma2(a2, h23.x, w); ffma2(a3, h23.y, w);
                ffma2(a4, h45.x, w); ffma2(a5, h45.y, w);
                ffma2(a6, h67.x, w); ffma2(a7, h67.y, w);
            }
            // mid-loop: spin on LOCAL ctrl word + prefetch ep/pp
            {
                u32 w;
                do { w = ld_vol_sh(ctrl_addr); } while ((int)(w >> 12) < s);
                int tgt = (int)(w & 63u), adjv = (int)((w >> 6) & 63u);
                __pipeline_memcpy_async(&epp[rrow * 128 + c4],
                                        &g_embP[((int)q * Vn + tgt) * 128 + c4], 16);
                __pipeline_memcpy_async(&ppp[rrow * 128 + c4],
                    &g_proj[((((size_t)(g * CL + (int)q) * 8 + rrow) * Tn + adjv) * 128) + c4], 16);
                __pipeline_commit();
            }
#pragma unroll 8
            for (int kk = 32; kk < 64; kk++) {
                ull w = wt[kk * 64];
                ulonglong2 h01 = hp[kk * 4 + 0], h23 = hp[kk * 4 + 1];
                ulonglong2 h45 = hp[kk * 4 + 2], h67 = hp[kk * 4 + 3];
                ffma2(a0, h01.x, w); ffma2(a1, h01.y, w);
                ffma2(a2, h23.x, w); ffma2(a3, h23.y, w);
                ffma2(a4, h45.x, w); ffma2(a5, h45.y, w);
                ffma2(a6, h67.x, w); ffma2(a7, h67.y, w);
            }
            __pipeline_wait_prior(0);
            {
                ull* zd = zpu + kq * 512 + p;
                zd[0 * 64] = a0; zd[1 * 64] = a1; zd[2 * 64] = a2; zd[3 * 64] = a3;
                zd[4 * 64] = a4; zd[5 * 64] = a5; zd[6 * 64] = a6; zd[7 * 64] = a7;
            }
        }
        __syncthreads();   // (a)

        // ---- pointwise (tid<256) ----
        if (tid < 256) {
            ulonglong2 k0 = *(const ulonglong2*)(zpu + 0 * 512 + pr * 64 + 2 * pu);
            ulonglong2 k1 = *(const ulonglong2*)(zpu + 1 * 512 + pr * 64 + 2 * pu);
            ulonglong2 k2 = *(const ulonglong2*)(zpu + 2 * 512 + pr * 64 + 2 * pu);
            ulonglong2 k3 = *(const ulonglong2*)(zpu + 3 * 512 + pr * 64 + 2 * pu);
            ull s0 = add2(add2(k0.x, k1.x), add2(k2.x, k3.x));
            ull s1 = add2(add2(k0.y, k1.y), add2(k2.y, k3.y));
            float4 ep = *(const float4*)&epp[pr * 128 + 4 * pu];
            float4 pq = *(const float4*)&ppp[pr * 128 + 4 * pu];
            float2 zif = unpack2(s0);
            float2 zgo = unpack2(s1);
            float zi = zif.x + ep.x + pq.x;
            float zf = zif.y + ep.y + pq.y;
            float zg = zgo.x + ep.z + pq.z;
            float zo = zgo.y + ep.w + pq.w;
            float cold = cst[tid];
            float c2 = sigm(zf) * cold + sigm(zi) * tanhf(zg);
            float h2v = sigm(zo) * tanhf(c2);
            cst[tid] = c2;
            h2s[pu * 8 + pr] = h2v;
            hdA[((s + 1) & 1) * 2048 + (32 * (int)q + pu) * 8 + pr] = pack2(h2v, h2v);
        }
        __syncthreads();   // (b)

        // ---- control warp: broadcast h(s+1) via bulk DSMEM copies ----
        if (tid >= 256 && lane < 7 && s + 1 < Sn) {
            FENCE_ASYNC();
            u32 d = (q + 1 + (u32)lane) & 7u;
            u32 off = (HD_OFF + (((s + 1) & 1) * 2048 + (int)q * 256) * 2) * 4;  // ull->bytes
            bulk_dsmem_(mapa_(smbase + off, d), smbase + off, HB_BYTES,
                        mapa_(mbH[(s + 1) & 1], d));
            BULK_COMMIT();
        }
        // ---- workers: partial logits into local plg ----
        if (tid < 256) {
            int v = tid & 63, rr2 = tid >> 6;
            if (v < Vn) {
                float pa0 = 0.f, pa1 = 0.f;
#pragma unroll 8
                for (int ul = 0; ul < 32; ul++) {
                    float wv = WoS[ul * Vn + v];
                    pa0 += h2s[ul * 8 + rr2] * wv;
                    pa1 += h2s[ul * 8 + rr2 + 4] * wv;
                }
                plg[rr2 * 48 + v] = pa0;
                plg[(rr2 + 4) * 48 + v] = pa1;
            }
        }
        __syncthreads();   // (c)

        if (tid >= 256) {
            // ---- send plog rows to their owners ----
            if (lane < 7) {
                FENCE_ASYNC();
                u32 r = (q + 1 + (u32)lane) & 7u;     // dest owner = row r
                u32 dst_off = (PIN_OFF + (s & 1) * 384 + (int)q * 48) * 4;
                u32 src_off = (PLG_OFF + (int)r * 48) * 4;
                bulk_dsmem_(mapa_(smbase + dst_off, r), smbase + src_off, PL_BYTES,
                            mapa_(mbP[s & 1], r));
                BULK_COMMIT();
            }
            // ---- wait all partials, reduce + argmax + publish ctrl ----
            mbar_wait_(mbP[s & 1], (u32)((s >> 1) & 1));
            const float* pin = smf + PIN_OFF + (s & 1) * 384;
            float sA = 0.f, sB = 0.f;
            {
                float sum = bos[lane];
#pragma unroll
                for (int qq = 0; qq < CL; qq++)
                    sum += (qq == (int)q) ? plg[qq * 48 + lane] : pin[qq * 48 + lane];
                sA = sum;
            }
            if (lane < 16) {
                int v2 = lane + 32;
                float sum = bos[v2];
#pragma unroll
                for (int qq = 0; qq < CL; qq++)
                    sum += (qq == (int)q) ? plg[qq * 48 + v2] : pin[qq * 48 + v2];
                sB = sum;
            }
            float bv = sA; int bi = lane;
            if (lane < 16) { if (sB > bv) { bv = sB; bi = lane + 32; } }
#pragma unroll
            for (int off = 16; off; off >>= 1) {
                float ov = __shfl_xor_sync(0xffffffffu, bv, off);
                int   oi = __shfl_xor_sync(0xffffffffu, bi, off);
                if (ov > bv || (ov == bv && oi < bi)) { bv = ov; bi = oi; }
            }
            int preds = bi;
            int res = (hai == ts) ? 0 : preds;
            if (lane == 0) out[row * Sn + s] = (float)res;
            int inc = (preds == 2 && hai < ts) ? 1 : 0;
            hai += inc;
            int adjn = (hai < ts) ? hai : hai - 1;
            u32 word = ((u32)(s + 1) << 12) | ((u32)adjn << 6) | (u32)preds;
            if (lane < 8 && s + 1 < Sn)
                stc_u32(smbase + CTRL_OFF * 4 + (int)q * 4, lane, word);
        }
    }

    // ---- teardown: ensure source reads of all bulk copies complete, then cluster exit ----
    if (tid >= 256) BULK_WAIT_READ0();
    asm volatile("barrier.cluster.arrive.aligned;" ::: "memory");
    asm volatile("barrier.cluster.wait.aligned;" ::: "memory");
}

// ---------------- launch ----------------
extern "C" void kernel_launch(void* const* d_in, const int* in_sizes, int n_in,
                              void* d_out, int out_size) {
    (void)in_sizes; (void)n_in; (void)out_size;
    const float* inputs   = (const float*)d_in[0];
    const int*   word_ids = (const int*)d_in[1];
    const float* embed    = (const float*)d_in[2];
    const float* W        = (const float*)d_in[3];
    const float* Uw       = (const float*)d_in[4];
    const float* bias     = (const float*)d_in[5];
    const float* Wo       = (const float*)d_in[6];
    const float* bo       = (const float*)d_in[7];
    float* out = (float*)d_out;

    static int attr_done = 0;
    if (!attr_done) {
        cudaFuncSetAttribute(k_loop, cudaFuncAttributeMaxDynamicSharedMemorySize, SMEMB);
        attr_done = 1;
    }
    k_nop<<<1, 32>>>();
    k_prep<<<1217, 256>>>(word_ids, embed, W, bias, Uw);
    k_proj<<<dim3(8, 64), 256>>>(inputs, W);
    k_loop<<<NGRID, NTHR, SMEMB>>>(Wo, bo, out);
}